// round 16
// baseline (speedup 1.0000x reference)
#include <cuda_runtime.h>

// Denoise_17669495455833: batched FISTA QP (2 passes x 100 iters, rows of 512 fp32).
// R15: latency-bound 60% above the fma-op floor (12 warps/SM @166 regs). Halve state:
// pack the two HALVES of the SAME row per f32x2 pair: pair_j = (z[j], z[j+256]),
// j = 0..255, 8 pairs/lane. Both chains shift together -> identical shuffle structure;
// arrays shrink 16 -> 8 u64 (state 128 -> 64 regs) -> ~20 warps/SM.
// Seam (255<->256) via 4 broadcast shuffles + u64 shifts: pair<<32 = (ghost0, lo),
// pair>>32 = (hi, ghost0). DtD boundary rows -> HALF-masked per-lane constants
// (lane0 lo-half = rows 0,1; lane31 hi-half = rows 510,511), R14-style folding.
// One row per warp now: 16384 warps.

typedef unsigned long long u64;
#define FULL_MASK 0xffffffffu

__device__ u64 g_coefs[100];   // packed (coef, coef) per iteration

__device__ __forceinline__ u64 pk2(float lo, float hi) {
    u64 r;
    asm("mov.b64 %0, {%1,%2};" : "=l"(r) : "r"(__float_as_uint(lo)), "r"(__float_as_uint(hi)));
    return r;
}
__device__ __forceinline__ void upk2(u64 v, float& lo, float& hi) {
    unsigned a, b;
    asm("mov.b64 {%0,%1}, %2;" : "=r"(a), "=r"(b) : "l"(v));
    lo = __uint_as_float(a); hi = __uint_as_float(b);
}
__device__ __forceinline__ u64 fma2(u64 a, u64 b, u64 c) {
    u64 d;
    asm("fma.rn.f32x2 %0, %1, %2, %3;" : "=l"(d) : "l"(a), "l"(b), "l"(c));
    return d;
}
__device__ __forceinline__ u64 add2(u64 a, u64 b) {
    u64 d;
    asm("add.rn.f32x2 %0, %1, %2;" : "=l"(d) : "l"(a), "l"(b));
    return d;
}
__device__ __forceinline__ u64 sub2(u64 a, u64 b) {
    u64 d;
    asm("sub.rn.f32x2 %0, %1, %2;" : "=l"(d) : "l"(a), "l"(b));
    return d;
}
__device__ __forceinline__ u64 mul2(u64 a, u64 b) {
    u64 d;
    asm("mul.rn.f32x2 %0, %1, %2;" : "=l"(d) : "l"(a), "l"(b));
    return d;
}
__device__ __forceinline__ u64 rep2(float f) {
    unsigned u = __float_as_uint(f);
    return ((u64)u << 32) | (u64)u;
}

__global__ void coef_setup_kernel() {
    if (threadIdx.x == 0 && blockIdx.x == 0) {
        float t = 1.0f;
        for (int i = 0; i < 100; ++i) {
            float tn = 0.5f * (1.0f + sqrtf(fmaf(4.0f * t, t, 1.0f)));
            float c  = (t - 1.0f) / tn;
            unsigned u = __float_as_uint(c);
            g_coefs[i] = ((u64)u << 32) | (u64)u;
            t = tn;
        }
    }
}

__global__ void __launch_bounds__(64)
denoise_fista13_kernel(const float* __restrict__ in, float* __restrict__ out, int nrows)
{
    const int gw   = (int)((blockIdx.x * blockDim.x + threadIdx.x) >> 5);  // warp = ONE row
    const int lane = (int)(threadIdx.x & 31);
    if (gw >= nrows) return;

    const float* rp = in + (size_t)gw * 512;

    // pair_j = (elem j, elem j+256); lane l owns pairs 8l..8l+7
    u64 y[8], w[8], x[8], z[8];
    {
        float4 lo0 = *reinterpret_cast<const float4*>(rp + lane * 8);
        float4 lo1 = *reinterpret_cast<const float4*>(rp + lane * 8 + 4);
        float4 hi0 = *reinterpret_cast<const float4*>(rp + 256 + lane * 8);
        float4 hi1 = *reinterpret_cast<const float4*>(rp + 256 + lane * 8 + 4);
        y[0] = pk2(lo0.x, hi0.x); y[1] = pk2(lo0.y, hi0.y);
        y[2] = pk2(lo0.z, hi0.z); y[3] = pk2(lo0.w, hi0.w);
        y[4] = pk2(lo1.x, hi1.x); y[5] = pk2(lo1.y, hi1.y);
        y[6] = pk2(lo1.z, hi1.z); y[7] = pk2(lo1.w, hi1.w);
    }

    // LAM = 10, step = 1/322.
    // v = z + CZY*(z-y) + CDT*DtD(z),  CZY = -2/322, CDT = -20/322. Precombined:
    const float STEPf = 1.0f / 322.0f;
    const float CZYf  = -2.0f * STEPf;
    const float CDTf  = -2.0f * 10.0f * STEPf;
    const float CAf   = 1.0f + CZYf + 6.0f * CDTf;    // z_j
    const float CBf   = -4.0f * CDTf;                 // z_{j+-1}
    const float q1 = -5.0f * CDTf, q2 = 2.0f * CDTf, q3 = -1.0f * CDTf;

    const bool first = (lane == 0);
    const bool last  = (lane == 31);

    // HALF-masked boundary constants:
    //   rows 0,1   live in LO half of lane0's k=0,1
    //   rows 510,511 live in HI half of lane31's k=6,7
    const u64 CA   = rep2(CAf);
    const u64 CAk0 = pk2(CAf + (first ? q1 : 0.0f), CAf);
    const u64 CAk1 = pk2(CAf + (first ? q3 : 0.0f), CAf);
    const u64 CAk6 = pk2(CAf, CAf + (last ? q3 : 0.0f));
    const u64 CAk7 = pk2(CAf, CAf + (last ? q1 : 0.0f));
    const u64 CB   = rep2(CBf);
    const u64 CBk0 = pk2(CBf + (first ? q2 : 0.0f), CBf);  // s1.lo = zR1.lo only at lane0 k0
    const u64 CBk7 = pk2(CBf, CBf + (last ? q2 : 0.0f));   // s1.hi = p1.hi only at lane31 k7
    const u64 CC   = rep2(CDTf);
    const u64 Q2F  = first ? pk2(q2, 0.0f) : 0ULL;         // extra fma at k=1 (on p1)
    const u64 Q2L  = last  ? pk2(0.0f, q2) : 0ULL;         // extra fma at k=6 (on zR1)
    const u64 CE   = rep2(-CZYf);

    #pragma unroll 1
    for (int pass = 0; pass < 2; ++pass) {
        #pragma unroll
        for (int k = 0; k < 8; ++k) {
            x[k] = y[k]; z[k] = y[k];          // x0 = proj(y) = y
            w[k] = mul2(y[k], CE);             // hoisted data term (constant per pass)
        }

        #pragma unroll 1
        for (int it = 0; it < 100; ++it) {
            const u64 coefP = g_coefs[it];

            // within-lane-chain neighbors (previous iterate)
            u64 zu7 = __shfl_up_sync  (FULL_MASK, z[7], 1);   // pair jj-1
            u64 zu6 = __shfl_up_sync  (FULL_MASK, z[6], 1);   // pair jj-2
            u64 zd0 = __shfl_down_sync(FULL_MASK, z[0], 1);   // pair jj+1
            u64 zd1 = __shfl_down_sync(FULL_MASK, z[1], 1);   // pair jj+2
            // cross-seam / ghost pairs:
            //  P_m1 = pair -1  = (ghost0, e255) = pair255 << 32
            //  P_m2 = pair -2  = (ghost0, e254) = pair254 << 32
            //  P256 = pair 256 = (e256, ghost0) = pair0  >> 32
            //  P257 = pair 257 = (e257, ghost0) = pair1  >> 32
            u64 t7 = __shfl_sync(FULL_MASK, z[7], 31);
            u64 t6 = __shfl_sync(FULL_MASK, z[6], 31);
            u64 b0 = __shfl_sync(FULL_MASK, z[0], 0);
            u64 b1 = __shfl_sync(FULL_MASK, z[1], 0);
            u64 zm1_ = first ? (t7 << 32) : zu7;
            u64 zm2_ = first ? (t6 << 32) : zu6;
            u64 zp1_ = last  ? (b0 >> 32) : zd0;
            u64 zp2_ = last  ? (b1 >> 32) : zd1;

            // rotating window of OLD z values (z[] is overwritten in place)
            u64 p2 = zm2_, p1 = zm1_;

            #pragma unroll
            for (int k = 0; k < 8; ++k) {
                u64 zc  = z[k];                                 // old pair j
                u64 zR1 = (k <= 6) ? z[k + 1] : zp1_;           // old pair j+1
                u64 zR2 = (k <= 5) ? z[k + 2] : ((k == 6) ? zp1_ : zp2_);  // old pair j+2

                const u64 CAk = (k == 0) ? CAk0 : (k == 1) ? CAk1
                              : (k == 6) ? CAk6 : (k == 7) ? CAk7 : CA;
                const u64 CBk = (k == 0) ? CBk0 : (k == 7) ? CBk7 : CB;

                u64 s1 = add2(p1, zR1);
                u64 s2 = add2(p2, zR2);
                u64 v  = fma2(zc, CAk, w[k]);
                v = fma2(s1, CBk, v);
                v = fma2(s2, CC, v);
                if (k == 1) v = fma2(p1,  Q2F, v);   // row 1: q2 on z0 (lo half, lane0)
                if (k == 6) v = fma2(zR1, Q2L, v);   // row 510: q2 on z511 (hi half, lane31)

                // x_new = clip(v, 0, y)  (scalar FMNMX -> alu pipe)
                float vlo, vhi, ylo, yhi;
                upk2(v, vlo, vhi);
                upk2(y[k], ylo, yhi);
                u64 xn = pk2(fminf(fmaxf(vlo, 0.0f), ylo),
                             fminf(fmaxf(vhi, 0.0f), yhi));

                // z_new = x_new + coef*(x_new - x)
                u64 dx = sub2(xn, x[k]);
                z[k] = fma2(dx, coefP, xn);
                x[k] = xn;

                p2 = p1; p1 = zc;
            }
        }

        if (pass == 0) {
            #pragma unroll
            for (int k = 0; k < 8; ++k) {
                y[k] = x[k];                   // pass 2: y = pass-1 output
                w[k] = mul2(y[k], CE);
                z[k] = x[k];
            }
        }
    }

    float* op = out + (size_t)gw * 512;
    {
        float4 lo0, lo1, hi0, hi1;
        upk2(x[0], lo0.x, hi0.x); upk2(x[1], lo0.y, hi0.y);
        upk2(x[2], lo0.z, hi0.z); upk2(x[3], lo0.w, hi0.w);
        upk2(x[4], lo1.x, hi1.x); upk2(x[5], lo1.y, hi1.y);
        upk2(x[6], lo1.z, hi1.z); upk2(x[7], lo1.w, hi1.w);
        *reinterpret_cast<float4*>(op + lane * 8)       = lo0;
        *reinterpret_cast<float4*>(op + lane * 8 + 4)   = lo1;
        *reinterpret_cast<float4*>(op + 256 + lane * 8)     = hi0;
        *reinterpret_cast<float4*>(op + 256 + lane * 8 + 4) = hi1;
    }
}

extern "C" void kernel_launch(void* const* d_in, const int* in_sizes, int n_in,
                              void* d_out, int out_size)
{
    const float* in  = (const float*)d_in[0];
    float*       out = (float*)d_out;
    const int nrows  = in_sizes[0] / 512;            // 16384 rows
    coef_setup_kernel<<<1, 32>>>();
    const int warps  = nrows;                        // ONE row per warp
    const int blocks = (warps + 1) / 2;              // 2 warps per 64-thread block
    denoise_fista13_kernel<<<blocks, 64>>>(in, out, nrows);
}